// round 1
// baseline (speedup 1.0000x reference)
#include <cuda_runtime.h>

#define Nn 4096
#define NF 512
#define NH 64
#define H1 8
#define NC 16
#define WPR 128   // words per adjacency row (4096/32)

// ---------------- scratch (static device globals; no allocation) ----------------
__device__ unsigned g_adj[Nn * WPR];            // 2 MB bitmask
__device__ float g_feats1[H1 * Nn * NH];        // 8 MB
__device__ float g_s1[H1 * Nn];
__device__ float g_nb1[H1 * Nn];
__device__ float g_mx1[H1 * Nn];
__device__ float g_sm1[H1 * Nn];
__device__ float g_h[Nn * (H1 * NH)];           // 8 MB (layer-1 concat output)
__device__ float g_feats2[Nn * NC];
__device__ float g_s2[Nn];
__device__ float g_nb2[Nn];
__device__ float g_mx2[Nn];
__device__ float g_sm2[Nn];

// ---------------- K0: adjacency -> bitmask ----------------
__global__ void k_adjbits(const int* __restrict__ adj) {
    int gw = blockIdx.x * (blockDim.x >> 5) + (threadIdx.x >> 5);
    int lane = threadIdx.x & 31;
    int row = gw >> 2, q = gw & 3;                // each warp: 1024 j of one row
    const int* base = adj + (size_t)row * Nn + q * 1024;
    unsigned* wbase = g_adj + row * WPR + q * 32;
#pragma unroll 4
    for (int w = 0; w < 32; ++w) {
        unsigned m = __ballot_sync(0xffffffffu, base[w * 32 + lane] > 0);
        if (lane == 0) wbase[w] = m;
    }
}

// ---------------- K1: feats1[h] = x @ W1[h]  (M=4096,K=512,N=64, batch 8) ------
__global__ void k_gemm1(const float* __restrict__ x, const float* __restrict__ W1) {
    int h = blockIdx.y;
    int i0 = blockIdx.x * 64;
    __shared__ float As[16][65];   // [k][i], padded
    __shared__ float Bs[16][64];   // [k][f]
    int tid = threadIdx.x;
    int tx = tid & 15, ty = tid >> 4;
    float acc[4][4] = {};
    const float* Wh = W1 + (size_t)h * NF * NH;
    for (int k0 = 0; k0 < NF; k0 += 16) {
#pragma unroll
        for (int r = 0; r < 4; ++r) {
            int idx = tid + r * 256;
            int i = idx >> 4, k = idx & 15;
            As[k][i] = x[(size_t)(i0 + i) * NF + k0 + k];
        }
#pragma unroll
        for (int r = 0; r < 4; ++r) {
            int idx = tid + r * 256;
            int k = idx >> 6, f = idx & 63;
            Bs[k][f] = Wh[(size_t)(k0 + k) * NH + f];
        }
        __syncthreads();
#pragma unroll
        for (int k = 0; k < 16; ++k) {
            float a[4];
#pragma unroll
            for (int u = 0; u < 4; ++u) a[u] = As[k][ty * 4 + u];
            float4 b = *(const float4*)&Bs[k][tx * 4];
#pragma unroll
            for (int u = 0; u < 4; ++u) {
                acc[u][0] = fmaf(a[u], b.x, acc[u][0]);
                acc[u][1] = fmaf(a[u], b.y, acc[u][1]);
                acc[u][2] = fmaf(a[u], b.z, acc[u][2]);
                acc[u][3] = fmaf(a[u], b.w, acc[u][3]);
            }
        }
        __syncthreads();
    }
    float* outp = g_feats1 + ((size_t)h * Nn + i0) * NH;
#pragma unroll
    for (int u = 0; u < 4; ++u) {
        float4 v = make_float4(acc[u][0], acc[u][1], acc[u][2], acc[u][3]);
        *(float4*)&outp[(ty * 4 + u) * NH + tx * 4] = v;
    }
}

// ---------------- K1b: s1/nb1 = feats1 @ as1/an1 (one warp per (h,i)) ----------
__global__ void k_attnvec1(const float* __restrict__ as1, const float* __restrict__ an1) {
    int gw = blockIdx.x * (blockDim.x >> 5) + (threadIdx.x >> 5);   // h*Nn + i
    int lane = threadIdx.x & 31;
    int h = gw >> 12;
    const float* f = g_feats1 + (size_t)gw * NH;
    const float* av = as1 + h * NH;
    const float* nv = an1 + h * NH;
    float f0 = f[lane], f1 = f[lane + 32];
    float vs = f0 * av[lane] + f1 * av[lane + 32];
    float vn = f0 * nv[lane] + f1 * nv[lane + 32];
#pragma unroll
    for (int o = 16; o; o >>= 1) {
        vs += __shfl_xor_sync(0xffffffffu, vs, o);
        vn += __shfl_xor_sync(0xffffffffu, vn, o);
    }
    if (lane == 0) { g_s1[gw] = vs; g_nb1[gw] = vn; }
}

// ---------------- stats: per-row masked (max, sum-exp). leaky is monotone ------
__device__ __forceinline__ void stats_body(const float* __restrict__ s,
                                           const float* __restrict__ nb,
                                           float* __restrict__ mx,
                                           float* __restrict__ sm,
                                           int h, float* nbs) {
    int i = blockIdx.x * blockDim.x + threadIdx.x;
    float si = s[h * Nn + i];
    const float* nbh = nb + h * Nn;
    const unsigned* bi = g_adj + (size_t)i * WPR;

    float mnb = -1e30f;
    for (int t0 = 0; t0 < Nn; t0 += 1024) {
        __syncthreads();
#pragma unroll
        for (int u = 0; u < 4; ++u) nbs[threadIdx.x + u * 256] = nbh[t0 + threadIdx.x + u * 256];
        __syncthreads();
        for (int w = 0; w < 32; ++w) {
            unsigned b = bi[(t0 >> 5) + w];
#pragma unroll
            for (int k = 0; k < 32; ++k) {
                float v = ((b >> k) & 1u) ? nbs[w * 32 + k] : -1e30f;
                mnb = fmaxf(mnb, v);
            }
        }
    }
    float m = si + mnb;
    m = fmaxf(m, 0.2f * m);   // leaky of the max == max of leaky (monotone)

    float tot = 0.f;
    for (int t0 = 0; t0 < Nn; t0 += 1024) {
        __syncthreads();
#pragma unroll
        for (int u = 0; u < 4; ++u) nbs[threadIdx.x + u * 256] = nbh[t0 + threadIdx.x + u * 256];
        __syncthreads();
        for (int w = 0; w < 32; ++w) {
            unsigned b = bi[(t0 >> 5) + w];
#pragma unroll
            for (int k = 0; k < 32; ++k) {
                float e = si + nbs[w * 32 + k];
                e = fmaxf(e, 0.2f * e);
                float p = ((b >> k) & 1u) ? __expf(e - m) : 0.f;
                tot += p;
            }
        }
    }
    mx[h * Nn + i] = m;
    sm[h * Nn + i] = tot;
}

__global__ void k_stats1() {
    __shared__ float nbs[1024];
    stats_body(g_s1, g_nb1, g_mx1, g_sm1, blockIdx.y, nbs);
}
__global__ void k_stats2() {
    __shared__ float nbs[1024];
    stats_body(g_s2, g_nb2, g_mx2, g_sm2, 0, nbs);
}

// ---------------- K2: layer-1 attention: h[:,h*64:...] = relu(P@feats1 + b1) ---
__global__ void k_attn1(const float* __restrict__ b1) {
    int h = blockIdx.y;
    int i0 = blockIdx.x * 64;
    int tid = threadIdx.x;
    __shared__ float Ps[64][68];   // [j][i], padded, 16B-aligned rows
    __shared__ float Fs[64][64];   // [j][f]
    __shared__ float nbs[64];

    const float* fh = g_feats1 + (size_t)h * Nn * NH;
    int pr = tid >> 2, pj4 = tid & 3;      // stage-1: thread = (row pr, j-phase pj4)
    int irow = i0 + pr;
    float si = g_s1[h * Nn + irow];
    float mi = g_mx1[h * Nn + irow];
    float inv = 1.0f / g_sm1[h * Nn + irow];
    const unsigned* bi = g_adj + (size_t)irow * WPR;
    int tx = tid & 15, ty = tid >> 4;      // stage-2: 16x16, thread = 4x4 tile
    float acc[4][4] = {};

    for (int jt = 0; jt < Nn / 64; ++jt) {
        __syncthreads();
        const float4* fsrc = (const float4*)(fh + (size_t)jt * 64 * NH);
        float4* fdst = (float4*)(&Fs[0][0]);
#pragma unroll
        for (int r = 0; r < 4; ++r) fdst[tid + r * 256] = fsrc[tid + r * 256];
        if (tid < 64) nbs[tid] = g_nb1[h * Nn + jt * 64 + tid];
        __syncthreads();

        unsigned w0 = bi[jt * 2], w1 = bi[jt * 2 + 1];
#pragma unroll
        for (int k = 0; k < 16; ++k) {
            int j = pj4 + (k << 2);
            unsigned bit = (j < 32) ? ((w0 >> j) & 1u) : ((w1 >> (j - 32)) & 1u);
            float e = si + nbs[j];
            e = fmaxf(e, 0.2f * e);
            Ps[j][pr] = bit ? (__expf(e - mi) * inv) : 0.0f;
        }
        __syncthreads();

#pragma unroll 8
        for (int j = 0; j < 64; ++j) {
            float4 a = *(const float4*)&Ps[j][ty * 4];
            float4 b = *(const float4*)&Fs[j][tx * 4];
            acc[0][0] = fmaf(a.x, b.x, acc[0][0]);
            acc[0][1] = fmaf(a.x, b.y, acc[0][1]);
            acc[0][2] = fmaf(a.x, b.z, acc[0][2]);
            acc[0][3] = fmaf(a.x, b.w, acc[0][3]);
            acc[1][0] = fmaf(a.y, b.x, acc[1][0]);
            acc[1][1] = fmaf(a.y, b.y, acc[1][1]);
            acc[1][2] = fmaf(a.y, b.z, acc[1][2]);
            acc[1][3] = fmaf(a.y, b.w, acc[1][3]);
            acc[2][0] = fmaf(a.z, b.x, acc[2][0]);
            acc[2][1] = fmaf(a.z, b.y, acc[2][1]);
            acc[2][2] = fmaf(a.z, b.z, acc[2][2]);
            acc[2][3] = fmaf(a.z, b.w, acc[2][3]);
            acc[3][0] = fmaf(a.w, b.x, acc[3][0]);
            acc[3][1] = fmaf(a.w, b.y, acc[3][1]);
            acc[3][2] = fmaf(a.w, b.z, acc[3][2]);
            acc[3][3] = fmaf(a.w, b.w, acc[3][3]);
        }
    }
    // epilogue: + b1, relu  (elu(relu(x)) == relu(x))
#pragma unroll
    for (int u = 0; u < 4; ++u) {
        int row = i0 + ty * 4 + u;
        float4 v;
        v.x = fmaxf(acc[u][0] + b1[h * NH + tx * 4 + 0], 0.f);
        v.y = fmaxf(acc[u][1] + b1[h * NH + tx * 4 + 1], 0.f);
        v.z = fmaxf(acc[u][2] + b1[h * NH + tx * 4 + 2], 0.f);
        v.w = fmaxf(acc[u][3] + b1[h * NH + tx * 4 + 3], 0.f);
        *(float4*)&g_h[(size_t)row * (H1 * NH) + h * NH + tx * 4] = v;
    }
}

// ---------------- K3: feats2 = h @ W2 ; s2/nb2 fused in epilogue ---------------
__global__ void k_gemm2(const float* __restrict__ W2, const float* __restrict__ as2,
                        const float* __restrict__ an2) {
    __shared__ float Ws[NF * NC];   // 32 KB
    int tid = threadIdx.x;
    for (int u = tid; u < NF * NC; u += 256) Ws[u] = W2[u];
    __syncthreads();
    int i = blockIdx.x * 256 + tid;
    const float* hr = g_h + (size_t)i * NF;
    float acc[NC] = {};
    for (int k = 0; k < NF; k += 4) {
        float4 xv = *(const float4*)&hr[k];
#pragma unroll
        for (int f = 0; f < NC; ++f) {
            acc[f] = fmaf(xv.x, Ws[(k + 0) * NC + f], acc[f]);
            acc[f] = fmaf(xv.y, Ws[(k + 1) * NC + f], acc[f]);
            acc[f] = fmaf(xv.z, Ws[(k + 2) * NC + f], acc[f]);
            acc[f] = fmaf(xv.w, Ws[(k + 3) * NC + f], acc[f]);
        }
    }
    float sv = 0.f, nv = 0.f;
#pragma unroll
    for (int f = 0; f < NC; ++f) { sv = fmaf(acc[f], as2[f], sv); nv = fmaf(acc[f], an2[f], nv); }
    float4* fo = (float4*)&g_feats2[(size_t)i * NC];
    fo[0] = make_float4(acc[0], acc[1], acc[2], acc[3]);
    fo[1] = make_float4(acc[4], acc[5], acc[6], acc[7]);
    fo[2] = make_float4(acc[8], acc[9], acc[10], acc[11]);
    fo[3] = make_float4(acc[12], acc[13], acc[14], acc[15]);
    g_s2[i] = sv;
    g_nb2[i] = nv;
}

// ---------------- K4: layer-2 attention + relu + log_softmax -> out ------------
__global__ void k_attn2(const float* __restrict__ b2, float* __restrict__ out) {
    int i0 = blockIdx.x * 64;
    int tid = threadIdx.x;
    __shared__ float Ps[64][68];
    __shared__ float Fs[64][16];
    __shared__ float nbs[64];
    int pr = tid >> 2, pj4 = tid & 3;
    int irow = i0 + pr;
    float si = g_s2[irow], mi = g_mx2[irow], inv = 1.f / g_sm2[irow];
    const unsigned* bi = g_adj + (size_t)irow * WPR;
    int tx = tid & 15, tq = tid >> 4;      // thread: 4 rows x 1 class
    float acc[4] = {0.f, 0.f, 0.f, 0.f};

    for (int jt = 0; jt < Nn / 64; ++jt) {
        __syncthreads();
        ((float4*)&Fs[0][0])[tid] = ((const float4*)(g_feats2 + (size_t)jt * 64 * NC))[tid];
        if (tid < 64) nbs[tid] = g_nb2[jt * 64 + tid];
        __syncthreads();
        unsigned w0 = bi[jt * 2], w1 = bi[jt * 2 + 1];
#pragma unroll
        for (int k = 0; k < 16; ++k) {
            int j = pj4 + (k << 2);
            unsigned bit = (j < 32) ? ((w0 >> j) & 1u) : ((w1 >> (j - 32)) & 1u);
            float e = si + nbs[j];
            e = fmaxf(e, 0.2f * e);
            Ps[j][pr] = bit ? (__expf(e - mi) * inv) : 0.0f;
        }
        __syncthreads();
#pragma unroll 8
        for (int j = 0; j < 64; ++j) {
            float b = Fs[j][tx];
            float4 a = *(const float4*)&Ps[j][tq * 4];
            acc[0] = fmaf(a.x, b, acc[0]);
            acc[1] = fmaf(a.y, b, acc[1]);
            acc[2] = fmaf(a.z, b, acc[2]);
            acc[3] = fmaf(a.w, b, acc[3]);
        }
    }
    float bb = b2[tx];
#pragma unroll
    for (int u = 0; u < 4; ++u) {
        float v = fmaxf(acc[u] + bb, 0.f);
        float m = v;
#pragma unroll
        for (int o = 8; o; o >>= 1) m = fmaxf(m, __shfl_xor_sync(0xffffffffu, m, o));
        float es = __expf(v - m);
#pragma unroll
        for (int o = 8; o; o >>= 1) es += __shfl_xor_sync(0xffffffffu, es, o);
        out[(size_t)(i0 + tq * 4 + u) * NC + tx] = v - (logf(es) + m);
    }
}

// ---------------- launcher ----------------
extern "C" void kernel_launch(void* const* d_in, const int* in_sizes, int n_in,
                              void* d_out, int out_size) {
    (void)in_sizes; (void)n_in; (void)out_size;
    const float* x   = (const float*)d_in[0];
    const int*   adj = (const int*)d_in[1];
    const float* W1  = (const float*)d_in[2];
    const float* b1  = (const float*)d_in[3];
    const float* as1 = (const float*)d_in[4];
    const float* an1 = (const float*)d_in[5];
    const float* W2  = (const float*)d_in[6];
    const float* b2  = (const float*)d_in[7];
    const float* as2 = (const float*)d_in[8];
    const float* an2 = (const float*)d_in[9];
    float* out = (float*)d_out;

    k_adjbits<<<2048, 256>>>(adj);
    k_gemm1<<<dim3(Nn / 64, H1), 256>>>(x, W1);
    k_attnvec1<<<(H1 * Nn) / 8, 256>>>(as1, an1);
    k_stats1<<<dim3(Nn / 256, H1), 256>>>();
    k_attn1<<<dim3(Nn / 64, H1), 256>>>(b1);
    k_gemm2<<<Nn / 256, 256>>>(W2, as2, an2);
    k_stats2<<<dim3(Nn / 256, 1), 256>>>();
    k_attn2<<<Nn / 64, 256>>>(b2, out);
}

// round 2
// speedup vs baseline: 1.4055x; 1.4055x over previous
#include <cuda_runtime.h>

#define Nn 4096
#define NF 512
#define NH 64
#define H1 8
#define NC 16
#define WPR 128   // words per adjacency row (4096/32)

// ---------------- scratch (static device globals; no allocation) ----------------
__device__ unsigned g_adj[Nn * WPR];            // 2 MB bitmask
__device__ float g_feats1[H1 * Nn * NH];        // 8 MB
__device__ float g_s1[H1 * Nn];
__device__ float g_nb1[H1 * Nn];
__device__ float g_sm1[H1 * Nn];
__device__ float g_h[Nn * (H1 * NH)];           // 8 MB (layer-1 concat output)
__device__ float g_feats2[Nn * NC];
__device__ float g_s2[Nn];
__device__ float g_nb2[Nn];
__device__ float g_sm2[Nn];

// packed f32x2 FMA: d = a*b + d (elementwise on packed halves)
__device__ __forceinline__ void ffma2(unsigned long long& d,
                                      unsigned long long a,
                                      unsigned long long b) {
    asm("fma.rn.f32x2 %0, %1, %2, %0;" : "+l"(d) : "l"(a), "l"(b));
}

// ---------------- K0: adjacency -> bitmask ----------------
__global__ void k_adjbits(const int* __restrict__ adj) {
    int gw = blockIdx.x * (blockDim.x >> 5) + (threadIdx.x >> 5);
    int lane = threadIdx.x & 31;
    int row = gw >> 2, q = gw & 3;                // each warp: 1024 j of one row
    const int* base = adj + (size_t)row * Nn + q * 1024;
    unsigned* wbase = g_adj + row * WPR + q * 32;
#pragma unroll 4
    for (int w = 0; w < 32; ++w) {
        unsigned m = __ballot_sync(0xffffffffu, base[w * 32 + lane] > 0);
        if (lane == 0) wbase[w] = m;
    }
}

// ---------------- K1: feats1[h] = x @ W1[h]  (FFMA2, duplicated A tile) --------
__global__ void k_gemm1(const float* __restrict__ x, const float* __restrict__ W1) {
    int h = blockIdx.y;
    int i0 = blockIdx.x * 64;
    __shared__ float As2[16][132];  // [k][2i] duplicated
    __shared__ float Bs[16][64];    // [k][f]
    int tid = threadIdx.x;
    int tx = tid & 15, ty = tid >> 4;
    unsigned long long acc[4][2] = {};
    const float* Wh = W1 + (size_t)h * NF * NH;
    for (int k0 = 0; k0 < NF; k0 += 16) {
#pragma unroll
        for (int r = 0; r < 4; ++r) {
            int idx = tid + r * 256;
            int i = idx >> 4, k = idx & 15;
            float v = x[(size_t)(i0 + i) * NF + k0 + k];
            *(float2*)&As2[k][2 * i] = make_float2(v, v);
        }
#pragma unroll
        for (int r = 0; r < 4; ++r) {
            int idx = tid + r * 256;
            int k = idx >> 6, f = idx & 63;
            Bs[k][f] = Wh[(size_t)(k0 + k) * NH + f];
        }
        __syncthreads();
#pragma unroll
        for (int k = 0; k < 16; ++k) {
            ulonglong2 a01 = *(const ulonglong2*)&As2[k][ty * 8];
            ulonglong2 a23 = *(const ulonglong2*)&As2[k][ty * 8 + 4];
            ulonglong2 bb  = *(const ulonglong2*)&Bs[k][tx * 4];
            ffma2(acc[0][0], a01.x, bb.x); ffma2(acc[0][1], a01.x, bb.y);
            ffma2(acc[1][0], a01.y, bb.x); ffma2(acc[1][1], a01.y, bb.y);
            ffma2(acc[2][0], a23.x, bb.x); ffma2(acc[2][1], a23.x, bb.y);
            ffma2(acc[3][0], a23.y, bb.x); ffma2(acc[3][1], a23.y, bb.y);
        }
        __syncthreads();
    }
    float* outp = g_feats1 + ((size_t)h * Nn + i0) * NH;
#pragma unroll
    for (int u = 0; u < 4; ++u) {
        float2 p0 = *(float2*)&acc[u][0];
        float2 p1 = *(float2*)&acc[u][1];
        float4 v = make_float4(p0.x, p0.y, p1.x, p1.y);
        *(float4*)&outp[(ty * 4 + u) * NH + tx * 4] = v;
    }
}

// ---------------- K1b: s1/nb1 = feats1 @ as1/an1 (one warp per (h,i)) ----------
__global__ void k_attnvec1(const float* __restrict__ as1, const float* __restrict__ an1) {
    int gw = blockIdx.x * (blockDim.x >> 5) + (threadIdx.x >> 5);   // h*Nn + i
    int lane = threadIdx.x & 31;
    int h = gw >> 12;
    const float* f = g_feats1 + (size_t)gw * NH;
    const float* av = as1 + h * NH;
    const float* nv = an1 + h * NH;
    float f0 = f[lane], f1 = f[lane + 32];
    float vs = f0 * av[lane] + f1 * av[lane + 32];
    float vn = f0 * nv[lane] + f1 * nv[lane + 32];
#pragma unroll
    for (int o = 16; o; o >>= 1) {
        vs += __shfl_xor_sync(0xffffffffu, vs, o);
        vn += __shfl_xor_sync(0xffffffffu, vn, o);
    }
    if (lane == 0) { g_s1[gw] = vs; g_nb1[gw] = vn; }
}

// ---------------- stats: warp-per-row masked sum of exp(leaky(s+nb)) -----------
// No max-subtraction: softmax is shift-invariant; magnitudes are fp32-safe here.
__device__ __forceinline__ void stats_warp(const float* __restrict__ s,
                                           const float* __restrict__ nb,
                                           float* __restrict__ sm,
                                           int h, float* nbs) {
    int w = threadIdx.x >> 5, lane = threadIdx.x & 31;
    int i = blockIdx.x * 8 + w;
    float si = s[h * Nn + i];
    const unsigned* bi = g_adj + (size_t)i * WPR;
    const float* nbh = nb + h * Nn;
    float tot = 0.f;
    for (int c = 0; c < 4; ++c) {
        __syncthreads();
#pragma unroll
        for (int u = 0; u < 4; ++u)
            nbs[threadIdx.x + u * 256] = nbh[c * 1024 + threadIdx.x + u * 256];
        __syncthreads();
        unsigned b = bi[c * 32 + lane];
#pragma unroll
        for (int k = 0; k < 32; ++k) {
            int kk = (k + lane) & 31;           // lane-rotated: conflict-free LDS
            float v = si + nbs[lane * 32 + kk];
            v = fmaxf(v, 0.2f * v);
            float p = __expf(v);
            tot += ((b >> kk) & 1u) ? p : 0.f;
        }
    }
#pragma unroll
    for (int o = 16; o; o >>= 1) tot += __shfl_xor_sync(0xffffffffu, tot, o);
    if (lane == 0) sm[h * Nn + i] = tot;
}

__global__ void k_stats1() {
    __shared__ float nbs[1024];
    stats_warp(g_s1, g_nb1, g_sm1, blockIdx.y, nbs);
}
__global__ void k_stats2() {
    __shared__ float nbs[1024];
    stats_warp(g_s2, g_nb2, g_sm2, 0, nbs);
}

// ---------------- K2: layer-1 attention: h = relu(P@feats1 + b1), FFMA2 --------
__global__ void k_attn1(const float* __restrict__ b1) {
    int h = blockIdx.y;
    int i0 = blockIdx.x * 64;
    int tid = threadIdx.x;
    __shared__ float Ps2[64][132];  // [j][2i] duplicated P values
    __shared__ float Fs[64][64];    // [j][f]
    __shared__ float nbs[64];

    const float* fh = g_feats1 + (size_t)h * Nn * NH;
    int pr = tid >> 2, pj4 = tid & 3;      // stage-1: thread = (row pr, j-phase pj4)
    int irow = i0 + pr;
    float si = g_s1[h * Nn + irow];
    float inv = 1.0f / g_sm1[h * Nn + irow];
    const unsigned* bi = g_adj + (size_t)irow * WPR;
    int tx = tid & 15, ty = tid >> 4;      // stage-2: 16x16, thread = 4x4 tile
    unsigned long long acc[4][2] = {};

    for (int jt = 0; jt < Nn / 64; ++jt) {
        __syncthreads();
        const float4* fsrc = (const float4*)(fh + (size_t)jt * 64 * NH);
        float4* fdst = (float4*)(&Fs[0][0]);
#pragma unroll
        for (int r = 0; r < 4; ++r) fdst[tid + r * 256] = fsrc[tid + r * 256];
        if (tid < 64) nbs[tid] = g_nb1[h * Nn + jt * 64 + tid];
        __syncthreads();

        unsigned w0 = bi[jt * 2], w1 = bi[jt * 2 + 1];
#pragma unroll
        for (int k = 0; k < 16; ++k) {
            int j = pj4 + (k << 2);
            unsigned bit = (j < 32) ? ((w0 >> j) & 1u) : ((w1 >> (j - 32)) & 1u);
            float e = si + nbs[j];
            e = fmaxf(e, 0.2f * e);
            float p = __expf(e) * (bit ? inv : 0.0f);
            *(float2*)&Ps2[j][2 * pr] = make_float2(p, p);
        }
        __syncthreads();

#pragma unroll 4
        for (int j = 0; j < 64; ++j) {
            ulonglong2 a01 = *(const ulonglong2*)&Ps2[j][ty * 8];
            ulonglong2 a23 = *(const ulonglong2*)&Ps2[j][ty * 8 + 4];
            ulonglong2 bb  = *(const ulonglong2*)&Fs[j][tx * 4];
            ffma2(acc[0][0], a01.x, bb.x); ffma2(acc[0][1], a01.x, bb.y);
            ffma2(acc[1][0], a01.y, bb.x); ffma2(acc[1][1], a01.y, bb.y);
            ffma2(acc[2][0], a23.x, bb.x); ffma2(acc[2][1], a23.x, bb.y);
            ffma2(acc[3][0], a23.y, bb.x); ffma2(acc[3][1], a23.y, bb.y);
        }
    }
    // epilogue: + b1, relu  (elu(relu(x)) == relu(x))
#pragma unroll
    for (int u = 0; u < 4; ++u) {
        int row = i0 + ty * 4 + u;
        float2 p0 = *(float2*)&acc[u][0];
        float2 p1 = *(float2*)&acc[u][1];
        float4 v;
        v.x = fmaxf(p0.x + b1[h * NH + tx * 4 + 0], 0.f);
        v.y = fmaxf(p0.y + b1[h * NH + tx * 4 + 1], 0.f);
        v.z = fmaxf(p1.x + b1[h * NH + tx * 4 + 2], 0.f);
        v.w = fmaxf(p1.y + b1[h * NH + tx * 4 + 3], 0.f);
        *(float4*)&g_h[(size_t)row * (H1 * NH) + h * NH + tx * 4] = v;
    }
}

// ---------------- K3: feats2 = h @ W2 ; s2/nb2 fused in epilogue ---------------
__global__ void k_gemm2(const float* __restrict__ W2, const float* __restrict__ as2,
                        const float* __restrict__ an2) {
    __shared__ float Ws[NF * NC];   // 32 KB
    int tid = threadIdx.x;
    for (int u = tid; u < NF * NC; u += 256) Ws[u] = W2[u];
    __syncthreads();
    int i = blockIdx.x * 256 + tid;
    const float* hr = g_h + (size_t)i * NF;
    float acc[NC] = {};
    for (int k = 0; k < NF; k += 4) {
        float4 xv = *(const float4*)&hr[k];
#pragma unroll
        for (int f = 0; f < NC; ++f) {
            acc[f] = fmaf(xv.x, Ws[(k + 0) * NC + f], acc[f]);
            acc[f] = fmaf(xv.y, Ws[(k + 1) * NC + f], acc[f]);
            acc[f] = fmaf(xv.z, Ws[(k + 2) * NC + f], acc[f]);
            acc[f] = fmaf(xv.w, Ws[(k + 3) * NC + f], acc[f]);
        }
    }
    float sv = 0.f, nv = 0.f;
#pragma unroll
    for (int f = 0; f < NC; ++f) { sv = fmaf(acc[f], as2[f], sv); nv = fmaf(acc[f], an2[f], nv); }
    float4* fo = (float4*)&g_feats2[(size_t)i * NC];
    fo[0] = make_float4(acc[0], acc[1], acc[2], acc[3]);
    fo[1] = make_float4(acc[4], acc[5], acc[6], acc[7]);
    fo[2] = make_float4(acc[8], acc[9], acc[10], acc[11]);
    fo[3] = make_float4(acc[12], acc[13], acc[14], acc[15]);
    g_s2[i] = sv;
    g_nb2[i] = nv;
}

// ---------------- K4: layer-2 attention + relu + log_softmax -> out ------------
__global__ void k_attn2(const float* __restrict__ b2, float* __restrict__ out) {
    int i0 = blockIdx.x * 64;
    int tid = threadIdx.x;
    __shared__ float Ps[64][68];
    __shared__ float Fs[64][16];
    __shared__ float nbs[64];
    int pr = tid >> 2, pj4 = tid & 3;
    int irow = i0 + pr;
    float si = g_s2[irow], inv = 1.f / g_sm2[irow];
    const unsigned* bi = g_adj + (size_t)irow * WPR;
    int tx = tid & 15, tq = tid >> 4;      // thread: 4 rows x 1 class
    float acc[4] = {0.f, 0.f, 0.f, 0.f};

    for (int jt = 0; jt < Nn / 64; ++jt) {
        __syncthreads();
        ((float4*)&Fs[0][0])[tid] = ((const float4*)(g_feats2 + (size_t)jt * 64 * NC))[tid];
        if (tid < 64) nbs[tid] = g_nb2[jt * 64 + tid];
        __syncthreads();
        unsigned w0 = bi[jt * 2], w1 = bi[jt * 2 + 1];
#pragma unroll
        for (int k = 0; k < 16; ++k) {
            int j = pj4 + (k << 2);
            unsigned bit = (j < 32) ? ((w0 >> j) & 1u) : ((w1 >> (j - 32)) & 1u);
            float e = si + nbs[j];
            e = fmaxf(e, 0.2f * e);
            Ps[j][pr] = __expf(e) * (bit ? inv : 0.0f);
        }
        __syncthreads();
#pragma unroll 8
        for (int j = 0; j < 64; ++j) {
            float b = Fs[j][tx];
            float4 a = *(const float4*)&Ps[j][tq * 4];
            acc[0] = fmaf(a.x, b, acc[0]);
            acc[1] = fmaf(a.y, b, acc[1]);
            acc[2] = fmaf(a.z, b, acc[2]);
            acc[3] = fmaf(a.w, b, acc[3]);
        }
    }
    float bb = b2[tx];
#pragma unroll
    for (int u = 0; u < 4; ++u) {
        float v = fmaxf(acc[u] + bb, 0.f);
        float m = v;
#pragma unroll
        for (int o = 8; o; o >>= 1) m = fmaxf(m, __shfl_xor_sync(0xffffffffu, m, o));
        float es = __expf(v - m);
#pragma unroll
        for (int o = 8; o; o >>= 1) es += __shfl_xor_sync(0xffffffffu, es, o);
        out[(size_t)(i0 + tq * 4 + u) * NC + tx] = v - (logf(es) + m);
    }
}

// ---------------- launcher ----------------
extern "C" void kernel_launch(void* const* d_in, const int* in_sizes, int n_in,
                              void* d_out, int out_size) {
    (void)in_sizes; (void)n_in; (void)out_size;
    const float* x   = (const float*)d_in[0];
    const int*   adj = (const int*)d_in[1];
    const float* W1  = (const float*)d_in[2];
    const float* b1  = (const float*)d_in[3];
    const float* as1 = (const float*)d_in[4];
    const float* an1 = (const float*)d_in[5];
    const float* W2  = (const float*)d_in[6];
    const float* b2  = (const float*)d_in[7];
    const float* as2 = (const float*)d_in[8];
    const float* an2 = (const float*)d_in[9];
    float* out = (float*)d_out;

    k_adjbits<<<2048, 256>>>(adj);
    k_gemm1<<<dim3(Nn / 64, H1), 256>>>(x, W1);
    k_attnvec1<<<(H1 * Nn) / 8, 256>>>(as1, an1);
    k_stats1<<<dim3(Nn / 8, H1), 256>>>();
    k_attn1<<<dim3(Nn / 64, H1), 256>>>(b1);
    k_gemm2<<<Nn / 256, 256>>>(W2, as2, an2);
    k_stats2<<<dim3(Nn / 8, 1), 256>>>();
    k_attn2<<<Nn / 64, 256>>>(b2, out);
}

// round 4
// speedup vs baseline: 3.9791x; 2.8312x over previous
#include <cuda_runtime.h>
#include <cstdint>

#define Nn 4096
#define NF 512
#define NH 64
#define H1 8
#define NC 16
#define WPR 128   // words per adjacency row (4096/32)

// ---------------- scratch (static device globals; no allocation) ----------------
__device__ unsigned g_adj[Nn * WPR];            // 2 MB bitmask
__device__ float g_feats1[H1 * Nn * NH];        // 8 MB  [h][i][f]  (fp32)
__device__ float g_ft[H1 * NH * Nn];            // 8 MB  [h][f][j]  (tf32-rounded)
__device__ float g_wt[H1 * NH * NF];            // 1 MB  [h][f][k]  (tf32-rounded W1^T)
__device__ float2 g_EG1[H1 * Nn];               // (exp(s), exp(.2 s))
__device__ float2 g_FH1[H1 * Nn];               // (exp(nb), exp(.2 nb))
__device__ float g_h[Nn * (H1 * NH)];           // 8 MB (layer-1 concat output)
__device__ float g_feats2[Nn * NC];
__device__ float2 g_EG2[Nn];
__device__ float2 g_FH2[Nn];
__device__ float g_Rs1[H1 * Nn];                // (unused spare)

// ---------------- helpers ----------------
__device__ __forceinline__ uint32_t tf32r(float f) {
    uint32_t r; asm("cvt.rna.tf32.f32 %0, %1;" : "=r"(r) : "f"(f)); return r;
}
__device__ __forceinline__ float tf32f(float f) {
    uint32_t r = tf32r(f); return __uint_as_float(r);
}
__device__ __forceinline__ void mma_tf32(float* c,
                                         uint32_t a0, uint32_t a1, uint32_t a2, uint32_t a3,
                                         uint32_t b0, uint32_t b1) {
    asm volatile(
        "mma.sync.aligned.m16n8k8.row.col.f32.tf32.tf32.f32 "
        "{%0,%1,%2,%3}, {%4,%5,%6,%7}, {%8,%9}, {%0,%1,%2,%3};"
        : "+f"(c[0]), "+f"(c[1]), "+f"(c[2]), "+f"(c[3])
        : "r"(a0), "r"(a1), "r"(a2), "r"(a3), "r"(b0), "r"(b1));
}

// ---------------- K0: adjacency -> bitmask ----------------
__global__ void k_adjbits(const int* __restrict__ adj) {
    int gw = blockIdx.x * (blockDim.x >> 5) + (threadIdx.x >> 5);
    int lane = threadIdx.x & 31;
    int row = gw >> 2, q = gw & 3;
    const int* base = adj + (size_t)row * Nn + q * 1024;
    unsigned* wbase = g_adj + row * WPR + q * 32;
#pragma unroll 4
    for (int w = 0; w < 32; ++w) {
        unsigned m = __ballot_sync(0xffffffffu, base[w * 32 + lane] > 0);
        if (lane == 0) wbase[w] = m;
    }
}

// ---------------- K0b: W1 [h][k][f] -> g_wt [h][f][k], tf32-rounded ------------
__global__ void k_wt(const float* __restrict__ W1) {
    __shared__ float t[32][33];
    int h = blockIdx.z;
    int kt = blockIdx.x * 32, ft = blockIdx.y * 32;
    int x = threadIdx.x, y = threadIdx.y;
    const float* src = W1 + (size_t)h * NF * NH;
#pragma unroll
    for (int r = y; r < 32; r += 8)
        t[r][x] = src[(size_t)(kt + r) * NH + ft + x];
    __syncthreads();
    float* dst = g_wt + (size_t)h * NH * NF;
#pragma unroll
    for (int r = y; r < 32; r += 8)
        dst[(size_t)(ft + r) * NF + kt + x] = tf32f(t[x][r]);
}

// ---------------- K1: feats1[h] = x @ W1[h]  via mma.sync tf32 -----------------
// block: 256 thr = 8 warps; warp w: rows i0 + w*16 .. +15 ; all 64 cols; K=512
__global__ void __launch_bounds__(256, 2) k_gemm1_mma(const float* __restrict__ x) {
    int h = blockIdx.y;
    int i0 = blockIdx.x * 128;
    int tid = threadIdx.x, wid = tid >> 5, lane = tid & 31;
    int gid = lane >> 2, tig = lane & 3;
    __shared__ float Xs[128][40];   // A chunk [row][k], tf32-rounded
    __shared__ float Wt_s[64][40];  // B chunk [f][k], pre-rounded

    int r0 = wid * 16 + gid, r1 = r0 + 8;
    float c[8][4] = {};

    int srow = tid >> 1, shalf = tid & 1;          // Xs staging
    int sf = tid >> 2, sq = tid & 3;               // Wt staging
    const float* xsrc = x + (size_t)(i0 + srow) * NF + shalf * 16;
    const float* wsrc = g_wt + ((size_t)h * NH + sf) * NF + sq * 8;

    for (int kc = 0; kc < NF / 32; ++kc) {
        __syncthreads();
#pragma unroll
        for (int v = 0; v < 4; ++v) {
            float4 t = *(const float4*)(xsrc + kc * 32 + v * 4);
            t.x = tf32f(t.x); t.y = tf32f(t.y); t.z = tf32f(t.z); t.w = tf32f(t.w);
            *(float4*)&Xs[srow][shalf * 16 + v * 4] = t;
        }
        {
            float4 v0 = *(const float4*)(wsrc + kc * 32);
            float4 v1 = *(const float4*)(wsrc + kc * 32 + 4);
            *(float4*)&Wt_s[sf][sq * 8] = v0;
            *(float4*)&Wt_s[sf][sq * 8 + 4] = v1;
        }
        __syncthreads();
#pragma unroll
        for (int ks = 0; ks < 4; ++ks) {
            int k0 = ks * 8 + 2 * tig;
            float2 a02 = *(const float2*)&Xs[r0][k0];
            float2 a13 = *(const float2*)&Xs[r1][k0];
            uint32_t a0 = __float_as_uint(a02.x), a2 = __float_as_uint(a02.y);
            uint32_t a1 = __float_as_uint(a13.x), a3 = __float_as_uint(a13.y);
#pragma unroll
            for (int nt = 0; nt < 8; ++nt) {
                float2 b = *(const float2*)&Wt_s[nt * 8 + gid][k0];
                mma_tf32(c[nt], a0, a1, a2, a3, __float_as_uint(b.x), __float_as_uint(b.y));
            }
        }
    }
    float* o0 = g_feats1 + ((size_t)h * Nn + i0 + r0) * NH;
    float* o1 = g_feats1 + ((size_t)h * Nn + i0 + r1) * NH;
#pragma unroll
    for (int nt = 0; nt < 8; ++nt) {
        int cc = nt * 8 + 2 * tig;
        *(float2*)(o0 + cc) = make_float2(c[nt][0], c[nt][1]);
        *(float2*)(o1 + cc) = make_float2(c[nt][2], c[nt][3]);
    }
}

// ---------------- K1t: transpose feats1 -> g_ft [h][f][j], tf32-rounded --------
__global__ void k_transp() {
    __shared__ float t[32][33];
    int h = blockIdx.z, jb = blockIdx.x, fb = blockIdx.y;
    int x = threadIdx.x, y = threadIdx.y;
    const float* src = g_feats1 + (size_t)h * Nn * NH;
#pragma unroll
    for (int r = y; r < 32; r += 8)
        t[r][x] = src[(size_t)(jb * 32 + r) * NH + fb * 32 + x];
    __syncthreads();
    float* dst = g_ft + (size_t)h * NH * Nn;
#pragma unroll
    for (int r = y; r < 32; r += 8)
        dst[(size_t)(fb * 32 + r) * Nn + jb * 32 + x] = tf32f(t[x][r]);
}

// ---------------- K1b: s/nb -> (E,G)/(F,H) factorized exps ---------------------
__global__ void k_attnvec1(const float* __restrict__ as1, const float* __restrict__ an1) {
    int gw = blockIdx.x * (blockDim.x >> 5) + (threadIdx.x >> 5);   // h*Nn + i
    int lane = threadIdx.x & 31;
    int h = gw >> 12;
    const float* f = g_feats1 + (size_t)gw * NH;
    const float* av = as1 + h * NH;
    const float* nv = an1 + h * NH;
    float f0 = f[lane], f1 = f[lane + 32];
    float vs = f0 * av[lane] + f1 * av[lane + 32];
    float vn = f0 * nv[lane] + f1 * nv[lane + 32];
#pragma unroll
    for (int o = 16; o; o >>= 1) {
        vs += __shfl_xor_sync(0xffffffffu, vs, o);
        vn += __shfl_xor_sync(0xffffffffu, vn, o);
    }
    if (lane == 0) {
        g_EG1[gw] = make_float2(__expf(vs), __expf(0.2f * vs));
        g_FH1[gw] = make_float2(__expf(vn), __expf(0.2f * vn));
    }
}

// ---------------- K2: layer-1 attention via mma.sync tf32 ----------------------
// block = (head h, 128 rows); warp = 16 rows x 64 cols; K = 4096 in chunks of 32.
// P generated in-register in fragment layout: P_ij = mask * max(E_i*F_j, G_i*H_j).
__global__ void __launch_bounds__(256, 2) k_attn1_mma(const float* __restrict__ b1) {
    int h = blockIdx.y;
    int i0 = blockIdx.x * 128;
    int tid = threadIdx.x, wid = tid >> 5, lane = tid & 31;
    int gid = lane >> 2, tig = lane & 3;

    __shared__ float Ft_s[64][40];     // B chunk [f][j], tf32-rounded
    __shared__ float2 FHs[32];
    __shared__ unsigned adjs[128];
    __shared__ float Rs[128];

    int r0 = wid * 16 + gid, r1 = r0 + 8;
    float2 eg0 = g_EG1[h * Nn + i0 + r0];
    float2 eg1 = g_EG1[h * Nn + i0 + r1];
    float c[8][4] = {};
    float rs0 = 0.f, rs1 = 0.f;

    int sf = tid >> 2, sq = tid & 3;
    const float* fsrc = g_ft + ((size_t)h * NH + sf) * Nn;
    const float2* fhsrc = g_FH1 + h * Nn;

    for (int jt = 0; jt < Nn / 32; ++jt) {
        __syncthreads();
        {
            float4 v0 = *(const float4*)(fsrc + jt * 32 + sq * 8);
            float4 v1 = *(const float4*)(fsrc + jt * 32 + sq * 8 + 4);
            *(float4*)&Ft_s[sf][sq * 8] = v0;
            *(float4*)&Ft_s[sf][sq * 8 + 4] = v1;
        }
        if (tid < 32) FHs[tid] = fhsrc[jt * 32 + tid];
        if (tid < 128) adjs[tid] = g_adj[(size_t)(i0 + tid) * WPR + jt];
        __syncthreads();

        unsigned w0 = adjs[r0], w1 = adjs[r1];
#pragma unroll
        for (int ks = 0; ks < 4; ++ks) {
            int j0 = ks * 8 + 2 * tig;
            float4 fh = *(const float4*)&FHs[j0];   // F_j0, H_j0, F_j0+1, H_j0+1
            float p00 = ((w0 >> j0) & 1u) ? fmaxf(eg0.x * fh.x, eg0.y * fh.y) : 0.f;
            float p01 = ((w0 >> (j0 + 1)) & 1u) ? fmaxf(eg0.x * fh.z, eg0.y * fh.w) : 0.f;
            float p10 = ((w1 >> j0) & 1u) ? fmaxf(eg1.x * fh.x, eg1.y * fh.y) : 0.f;
            float p11 = ((w1 >> (j0 + 1)) & 1u) ? fmaxf(eg1.x * fh.z, eg1.y * fh.w) : 0.f;
            rs0 += p00 + p01;
            rs1 += p10 + p11;
            uint32_t a0 = tf32r(p00), a1 = tf32r(p10), a2 = tf32r(p01), a3 = tf32r(p11);
#pragma unroll
            for (int nt = 0; nt < 8; ++nt) {
                float2 b = *(const float2*)&Ft_s[nt * 8 + gid][j0];
                mma_tf32(c[nt], a0, a1, a2, a3, __float_as_uint(b.x), __float_as_uint(b.y));
            }
        }
    }
    // full row sums: reduce over the 4 lanes of each quad (tig bits = lane bits 0,1)
    rs0 += __shfl_xor_sync(0xffffffffu, rs0, 1);
    rs0 += __shfl_xor_sync(0xffffffffu, rs0, 2);
    rs1 += __shfl_xor_sync(0xffffffffu, rs1, 1);
    rs1 += __shfl_xor_sync(0xffffffffu, rs1, 2);
    if (tig == 0) { Rs[r0] = rs0; Rs[r1] = rs1; }
    __syncthreads();

    float inv0 = 1.0f / Rs[r0];
    float inv1 = 1.0f / Rs[r1];
    const float* bh = b1 + h * NH;
    float* d0 = g_h + (size_t)(i0 + r0) * (H1 * NH) + h * NH;
    float* d1 = g_h + (size_t)(i0 + r1) * (H1 * NH) + h * NH;
#pragma unroll
    for (int nt = 0; nt < 8; ++nt) {
        int cc = nt * 8 + 2 * tig;
        float2 bb = *(const float2*)(bh + cc);
        float2 v0 = make_float2(fmaxf(c[nt][0] * inv0 + bb.x, 0.f),
                                fmaxf(c[nt][1] * inv0 + bb.y, 0.f));
        float2 v1 = make_float2(fmaxf(c[nt][2] * inv1 + bb.x, 0.f),
                                fmaxf(c[nt][3] * inv1 + bb.y, 0.f));
        *(float2*)(d0 + cc) = v0;
        *(float2*)(d1 + cc) = v1;
    }
}

// ---------------- K3: feats2 = h @ W2 ; factorized exps in epilogue ------------
__global__ void k_gemm2(const float* __restrict__ W2, const float* __restrict__ as2,
                        const float* __restrict__ an2) {
    __shared__ float Ws[NF * NC];
    int tid = threadIdx.x;
    for (int u = tid; u < NF * NC; u += 256) Ws[u] = W2[u];
    __syncthreads();
    int i = blockIdx.x * 256 + tid;
    const float* hr = g_h + (size_t)i * NF;
    float acc[NC] = {};
    for (int k = 0; k < NF; k += 4) {
        float4 xv = *(const float4*)&hr[k];
#pragma unroll
        for (int f = 0; f < NC; ++f) {
            acc[f] = fmaf(xv.x, Ws[(k + 0) * NC + f], acc[f]);
            acc[f] = fmaf(xv.y, Ws[(k + 1) * NC + f], acc[f]);
            acc[f] = fmaf(xv.z, Ws[(k + 2) * NC + f], acc[f]);
            acc[f] = fmaf(xv.w, Ws[(k + 3) * NC + f], acc[f]);
        }
    }
    float sv = 0.f, nv = 0.f;
#pragma unroll
    for (int f = 0; f < NC; ++f) { sv = fmaf(acc[f], as2[f], sv); nv = fmaf(acc[f], an2[f], nv); }
    float4* fo = (float4*)&g_feats2[(size_t)i * NC];
    fo[0] = make_float4(acc[0], acc[1], acc[2], acc[3]);
    fo[1] = make_float4(acc[4], acc[5], acc[6], acc[7]);
    fo[2] = make_float4(acc[8], acc[9], acc[10], acc[11]);
    fo[3] = make_float4(acc[12], acc[13], acc[14], acc[15]);
    g_EG2[i] = make_float2(__expf(sv), __expf(0.2f * sv));
    g_FH2[i] = make_float2(__expf(nv), __expf(0.2f * nv));
}

// ---------------- K4: layer-2 attention + relu + log_softmax -------------------
__global__ void k_attn2(const float* __restrict__ b2, float* __restrict__ out) {
    int i0 = blockIdx.x * 32;
    int tid = threadIdx.x;
    __shared__ float Ps[64][36];
    __shared__ float Fs[64][16];
    __shared__ float2 fhs[64];
    __shared__ float RsP[32][8];
    int pr = tid >> 3, pj = tid & 7;
    int irow = i0 + pr;
    float2 eg = g_EG2[irow];
    const unsigned* bi = g_adj + (size_t)irow * WPR;
    int tx = tid & 15, tq = tid >> 4;
    float acc0 = 0.f, acc1 = 0.f, rs = 0.f;

    for (int jt = 0; jt < Nn / 64; ++jt) {
        __syncthreads();
        ((float4*)&Fs[0][0])[tid] = ((const float4*)(g_feats2 + (size_t)jt * 64 * NC))[tid];
        if (tid < 64) fhs[tid] = g_FH2[jt * 64 + tid];
        __syncthreads();
        unsigned w0 = bi[jt * 2], w1 = bi[jt * 2 + 1];
#pragma unroll
        for (int k = 0; k < 8; ++k) {
            int j = pj + k * 8;
            unsigned bit = (j < 32) ? ((w0 >> j) & 1u) : ((w1 >> (j - 32)) & 1u);
            float2 fh = fhs[j];
            float p = bit ? fmaxf(eg.x * fh.x, eg.y * fh.y) : 0.f;
            rs += p;
            Ps[j][pr] = p;
        }
        __syncthreads();
#pragma unroll 8
        for (int j = 0; j < 64; ++j) {
            float b = Fs[j][tx];
            acc0 = fmaf(Ps[j][tq * 2], b, acc0);
            acc1 = fmaf(Ps[j][tq * 2 + 1], b, acc1);
        }
    }
    __syncthreads();
    RsP[pr][pj] = rs;
    __syncthreads();
    float s0 = 0.f, s1 = 0.f;
#pragma unroll
    for (int k = 0; k < 8; ++k) { s0 += RsP[tq * 2][k]; s1 += RsP[tq * 2 + 1][k]; }
    float bb = b2[tx];
    float v0 = fmaxf(acc0 / s0 + bb, 0.f);
    float v1 = fmaxf(acc1 / s1 + bb, 0.f);
    float m0 = v0, m1 = v1;
#pragma unroll
    for (int o = 8; o; o >>= 1) {
        m0 = fmaxf(m0, __shfl_xor_sync(0xffffffffu, m0, o));
        m1 = fmaxf(m1, __shfl_xor_sync(0xffffffffu, m1, o));
    }
    float e0 = __expf(v0 - m0), e1 = __expf(v1 - m1);
#pragma unroll
    for (int o = 8; o; o >>= 1) {
        e0 += __shfl_xor_sync(0xffffffffu, e0, o);
        e1 += __shfl_xor_sync(0xffffffffu, e1, o);
    }
    out[(size_t)(i0 + tq * 2 + 0) * NC + tx] = v0 - (logf(e0) + m0);
    out[(size_t)(i0 + tq * 2 + 1) * NC + tx] = v1 - (logf(e1) + m1);
}

// ---------------- launcher ----------------
extern "C" void kernel_launch(void* const* d_in, const int* in_sizes, int n_in,
                              void* d_out, int out_size) {
    (void)in_sizes; (void)n_in; (void)out_size;
    const float* x   = (const float*)d_in[0];
    const int*   adj = (const int*)d_in[1];
    const float* W1  = (const float*)d_in[2];
    const float* b1  = (const float*)d_in[3];
    const float* as1 = (const float*)d_in[4];
    const float* an1 = (const float*)d_in[5];
    const float* W2  = (const float*)d_in[6];
    const float* b2  = (const float*)d_in[7];
    const float* as2 = (const float*)d_in[8];
    const float* an2 = (const float*)d_in[9];
    float* out = (float*)d_out;

    k_adjbits<<<2048, 256>>>(adj);
    k_wt<<<dim3(NF / 32, NH / 32, H1), dim3(32, 8)>>>(W1);
    k_gemm1_mma<<<dim3(Nn / 128, H1), 256>>>(x);
    k_transp<<<dim3(Nn / 32, NH / 32, H1), dim3(32, 8)>>>();
    k_attnvec1<<<(H1 * Nn) / 8, 256>>>(as1, an1);
    k_attn1_mma<<<dim3(Nn / 128, H1), 256>>>(b1);
    k_gemm2<<<Nn / 256, 256>>>(W2, as2, an2);
    k_attn2<<<Nn / 32, 256>>>(b2, out);
}

// round 6
// speedup vs baseline: 5.0540x; 1.2701x over previous
#include <cuda_runtime.h>
#include <cuda_bf16.h>
#include <cstdint>

#define Nn 4096
#define NF 512
#define NH 64
#define H1 8
#define NC 16
#define WPR 128   // words per adjacency row (4096/32)

// ---------------- scratch (static device globals; no allocation) ----------------
__device__ unsigned g_adj[Nn * WPR];            // 2 MB bitmask
__device__ float g_feats1[H1 * Nn * NH];        // 8 MB  [h][i][f]  (fp32)
__device__ __nv_bfloat16 g_ftb[H1 * NH * Nn];   // 4 MB  [h][f][j]  (bf16)
__device__ float g_wt[H1 * NH * NF];            // 1 MB  [h][f][k]  (tf32-rounded W1^T)
__device__ float2 g_EG1[H1 * Nn];               // (exp(s), exp(.2 s))
__device__ float2 g_FH1[H1 * Nn];               // (exp(nb), exp(.2 nb))
__device__ float g_h[Nn * (H1 * NH)];           // 8 MB (layer-1 concat output)
__device__ float g_feats2[Nn * NC];
__device__ float2 g_EG2[Nn];
__device__ float2 g_FH2[Nn];

// ---------------- helpers ----------------
__device__ __forceinline__ uint32_t tf32r(float f) {
    uint32_t r; asm("cvt.rna.tf32.f32 %0, %1;" : "=r"(r) : "f"(f)); return r;
}
__device__ __forceinline__ float tf32f(float f) {
    uint32_t r = tf32r(f); return __uint_as_float(r);
}
__device__ __forceinline__ void mma_tf32(float* c,
                                         uint32_t a0, uint32_t a1, uint32_t a2, uint32_t a3,
                                         uint32_t b0, uint32_t b1) {
    asm volatile(
        "mma.sync.aligned.m16n8k8.row.col.f32.tf32.tf32.f32 "
        "{%0,%1,%2,%3}, {%4,%5,%6,%7}, {%8,%9}, {%0,%1,%2,%3};"
        : "+f"(c[0]), "+f"(c[1]), "+f"(c[2]), "+f"(c[3])
        : "r"(a0), "r"(a1), "r"(a2), "r"(a3), "r"(b0), "r"(b1));
}
__device__ __forceinline__ void mma_bf16(float* c,
                                         uint32_t a0, uint32_t a1, uint32_t a2, uint32_t a3,
                                         uint32_t b0, uint32_t b1) {
    asm volatile(
        "mma.sync.aligned.m16n8k16.row.col.f32.bf16.bf16.f32 "
        "{%0,%1,%2,%3}, {%4,%5,%6,%7}, {%8,%9}, {%0,%1,%2,%3};"
        : "+f"(c[0]), "+f"(c[1]), "+f"(c[2]), "+f"(c[3])
        : "r"(a0), "r"(a1), "r"(a2), "r"(a3), "r"(b0), "r"(b1));
}
__device__ __forceinline__ uint32_t pack_bf16x2(float lo, float hi) {
    uint32_t d;
    asm("cvt.rn.bf16x2.f32 %0, %1, %2;" : "=r"(d) : "f"(hi), "f"(lo));
    return d;
}

// ---------------- K0: adjacency -> bitmask ----------------
__global__ void k_adjbits(const int* __restrict__ adj) {
    int gw = blockIdx.x * (blockDim.x >> 5) + (threadIdx.x >> 5);
    int lane = threadIdx.x & 31;
    int row = gw >> 2, q = gw & 3;
    const int* base = adj + (size_t)row * Nn + q * 1024;
    unsigned* wbase = g_adj + row * WPR + q * 32;
#pragma unroll 4
    for (int w = 0; w < 32; ++w) {
        unsigned m = __ballot_sync(0xffffffffu, base[w * 32 + lane] > 0);
        if (lane == 0) wbase[w] = m;
    }
}

// ---------------- K0b: W1 [h][k][f] -> g_wt [h][f][k], tf32-rounded ------------
__global__ void k_wt(const float* __restrict__ W1) {
    __shared__ float t[32][33];
    int h = blockIdx.z;
    int kt = blockIdx.x * 32, ft = blockIdx.y * 32;
    int x = threadIdx.x, y = threadIdx.y;
    const float* src = W1 + (size_t)h * NF * NH;
#pragma unroll
    for (int r = y; r < 32; r += 8)
        t[r][x] = src[(size_t)(kt + r) * NH + ft + x];
    __syncthreads();
    float* dst = g_wt + (size_t)h * NH * NF;
#pragma unroll
    for (int r = y; r < 32; r += 8)
        dst[(size_t)(ft + r) * NF + kt + x] = tf32f(t[x][r]);
}

// ---------------- K1: feats1[h] = x @ W1[h]  via mma.sync tf32 -----------------
__global__ void __launch_bounds__(256, 2) k_gemm1_mma(const float* __restrict__ x) {
    int h = blockIdx.y;
    int i0 = blockIdx.x * 128;
    int tid = threadIdx.x, wid = tid >> 5, lane = tid & 31;
    int gid = lane >> 2, tig = lane & 3;
    __shared__ float Xs[128][40];
    __shared__ float Wt_s[64][40];

    int r0 = wid * 16 + gid, r1 = r0 + 8;
    float c[8][4] = {};

    int srow = tid >> 1, shalf = tid & 1;
    int sf = tid >> 2, sq = tid & 3;
    const float* xsrc = x + (size_t)(i0 + srow) * NF + shalf * 16;
    const float* wsrc = g_wt + ((size_t)h * NH + sf) * NF + sq * 8;

    for (int kc = 0; kc < NF / 32; ++kc) {
        __syncthreads();
#pragma unroll
        for (int v = 0; v < 4; ++v) {
            float4 t = *(const float4*)(xsrc + kc * 32 + v * 4);
            t.x = tf32f(t.x); t.y = tf32f(t.y); t.z = tf32f(t.z); t.w = tf32f(t.w);
            *(float4*)&Xs[srow][shalf * 16 + v * 4] = t;
        }
        {
            float4 v0 = *(const float4*)(wsrc + kc * 32);
            float4 v1 = *(const float4*)(wsrc + kc * 32 + 4);
            *(float4*)&Wt_s[sf][sq * 8] = v0;
            *(float4*)&Wt_s[sf][sq * 8 + 4] = v1;
        }
        __syncthreads();
#pragma unroll
        for (int ks = 0; ks < 4; ++ks) {
            int k0 = ks * 8 + 2 * tig;
            float2 a02 = *(const float2*)&Xs[r0][k0];
            float2 a13 = *(const float2*)&Xs[r1][k0];
            uint32_t a0 = __float_as_uint(a02.x), a2 = __float_as_uint(a02.y);
            uint32_t a1 = __float_as_uint(a13.x), a3 = __float_as_uint(a13.y);
#pragma unroll
            for (int nt = 0; nt < 8; ++nt) {
                float2 b = *(const float2*)&Wt_s[nt * 8 + gid][k0];
                mma_tf32(c[nt], a0, a1, a2, a3, __float_as_uint(b.x), __float_as_uint(b.y));
            }
        }
    }
    float* o0 = g_feats1 + ((size_t)h * Nn + i0 + r0) * NH;
    float* o1 = g_feats1 + ((size_t)h * Nn + i0 + r1) * NH;
#pragma unroll
    for (int nt = 0; nt < 8; ++nt) {
        int cc = nt * 8 + 2 * tig;
        *(float2*)(o0 + cc) = make_float2(c[nt][0], c[nt][1]);
        *(float2*)(o1 + cc) = make_float2(c[nt][2], c[nt][3]);
    }
}

// ---------------- K1t: transpose feats1 -> g_ftb [h][f][j], bf16 ---------------
__global__ void k_transp() {
    __shared__ float t[32][33];
    int h = blockIdx.z, jb = blockIdx.x, fb = blockIdx.y;
    int x = threadIdx.x, y = threadIdx.y;
    const float* src = g_feats1 + (size_t)h * Nn * NH;
#pragma unroll
    for (int r = y; r < 32; r += 8)
        t[r][x] = src[(size_t)(jb * 32 + r) * NH + fb * 32 + x];
    __syncthreads();
    __nv_bfloat16* dst = g_ftb + (size_t)h * NH * Nn;
#pragma unroll
    for (int r = y; r < 32; r += 8)
        dst[(size_t)(fb * 32 + r) * Nn + jb * 32 + x] = __float2bfloat16(t[x][r]);
}

// ---------------- K1b: s/nb -> (E,G)/(F,H) factorized exps ---------------------
__global__ void k_attnvec1(const float* __restrict__ as1, const float* __restrict__ an1) {
    int gw = blockIdx.x * (blockDim.x >> 5) + (threadIdx.x >> 5);   // h*Nn + i
    int lane = threadIdx.x & 31;
    int h = gw >> 12;
    const float* f = g_feats1 + (size_t)gw * NH;
    const float* av = as1 + h * NH;
    const float* nv = an1 + h * NH;
    float f0 = f[lane], f1 = f[lane + 32];
    float vs = f0 * av[lane] + f1 * av[lane + 32];
    float vn = f0 * nv[lane] + f1 * nv[lane + 32];
#pragma unroll
    for (int o = 16; o; o >>= 1) {
        vs += __shfl_xor_sync(0xffffffffu, vs, o);
        vn += __shfl_xor_sync(0xffffffffu, vn, o);
    }
    if (lane == 0) {
        g_EG1[gw] = make_float2(__expf(vs), __expf(0.2f * vs));
        g_FH1[gw] = make_float2(__expf(vn), __expf(0.2f * vn));
    }
}

// ---------------- K2: layer-1 attention via mma.sync bf16 m16n8k16 -------------
__global__ void __launch_bounds__(256, 2) k_attn1_mma(const float* __restrict__ b1) {
    int h = blockIdx.y;
    int i0 = blockIdx.x * 128;
    int tid = threadIdx.x, wid = tid >> 5, lane = tid & 31;
    int gid = lane >> 2, tig = lane & 3;

    __shared__ __align__(16) __nv_bfloat16 Ft_s[64][80];  // stride 160B
    __shared__ float2 FHs[64];
    __shared__ unsigned adjs[256];      // [row][word-half]
    __shared__ float Rs[128];

    int r0 = wid * 16 + gid, r1 = r0 + 8;
    float2 eg0 = g_EG1[h * Nn + i0 + r0];
    float2 eg1 = g_EG1[h * Nn + i0 + r1];
    float c[8][4] = {};
    float rs0 = 0.f, rs1 = 0.f;

    int sf = tid >> 2, sjq = (tid & 3) * 16;
    const __nv_bfloat16* fsrc = g_ftb + ((size_t)h * NH + sf) * Nn;
    const float2* fhsrc = g_FH1 + h * Nn;
    int arow = tid >> 1, ahalf = tid & 1;

    for (int jt = 0; jt < Nn / 64; ++jt) {
        __syncthreads();
        {   // Ft chunk: 16 bf16 per thread, pair-permuted store
            const uint4* s = (const uint4*)(fsrc + jt * 64 + sjq);
            uint4 v0 = s[0], v1 = s[1];
            uint32_t* dst = (uint32_t*)&Ft_s[sf][0];
            int base = sjq >> 1;
            dst[base + 0] = v0.x; dst[base + 2] = v0.y;
            dst[base + 4] = v0.z; dst[base + 6] = v0.w;
            dst[base + 1] = v1.x; dst[base + 3] = v1.y;
            dst[base + 5] = v1.z; dst[base + 7] = v1.w;
        }
        if (tid < 64) FHs[tid] = fhsrc[jt * 64 + tid];
        adjs[tid] = g_adj[(size_t)(i0 + arow) * WPR + jt * 2 + ahalf];
        __syncthreads();

        unsigned wa0 = adjs[r0 * 2], wb0 = adjs[r0 * 2 + 1];
        unsigned wa1 = adjs[r1 * 2], wb1 = adjs[r1 * 2 + 1];
#pragma unroll
        for (int ks = 0; ks < 4; ++ks) {
            int jb2 = ks * 16;
            unsigned sw0 = ((ks & 2) ? wb0 : wa0) >> ((ks & 1) * 16);
            unsigned sw1 = ((ks & 2) ? wb1 : wa1) >> ((ks & 1) * 16);
            int j0 = 2 * tig, j2 = j0 + 8;
            float2 fh0 = FHs[jb2 + j0];
            float2 fh1 = FHs[jb2 + j0 + 1];
            float2 fh2 = FHs[jb2 + j2];
            float2 fh3 = FHs[jb2 + j2 + 1];
            float p00 = ((sw0 >> j0) & 1u)       ? fmaxf(eg0.x * fh0.x, eg0.y * fh0.y) : 0.f;
            float p01 = ((sw0 >> (j0 + 1)) & 1u) ? fmaxf(eg0.x * fh1.x, eg0.y * fh1.y) : 0.f;
            float p02 = ((sw0 >> j2) & 1u)       ? fmaxf(eg0.x * fh2.x, eg0.y * fh2.y) : 0.f;
            float p03 = ((sw0 >> (j2 + 1)) & 1u) ? fmaxf(eg0.x * fh3.x, eg0.y * fh3.y) : 0.f;
            float p10 = ((sw1 >> j0) & 1u)       ? fmaxf(eg1.x * fh0.x, eg1.y * fh0.y) : 0.f;
            float p11 = ((sw1 >> (j0 + 1)) & 1u) ? fmaxf(eg1.x * fh1.x, eg1.y * fh1.y) : 0.f;
            float p12 = ((sw1 >> j2) & 1u)       ? fmaxf(eg1.x * fh2.x, eg1.y * fh2.y) : 0.f;
            float p13 = ((sw1 >> (j2 + 1)) & 1u) ? fmaxf(eg1.x * fh3.x, eg1.y * fh3.y) : 0.f;
            rs0 += (p00 + p01) + (p02 + p03);
            rs1 += (p10 + p11) + (p12 + p13);
            uint32_t a0 = pack_bf16x2(p00, p01);
            uint32_t a1 = pack_bf16x2(p10, p11);
            uint32_t a2 = pack_bf16x2(p02, p03);
            uint32_t a3 = pack_bf16x2(p12, p13);
#pragma unroll
            for (int nt = 0; nt < 8; ++nt) {
                uint2 bb = *(const uint2*)((const char*)&Ft_s[0][0] +
                                           (nt * 8 + gid) * 160 + ks * 32 + tig * 8);
                mma_bf16(c[nt], a0, a1, a2, a3, bb.x, bb.y);
            }
        }
    }
    rs0 += __shfl_xor_sync(0xffffffffu, rs0, 1);
    rs0 += __shfl_xor_sync(0xffffffffu, rs0, 2);
    rs1 += __shfl_xor_sync(0xffffffffu, rs1, 1);
    rs1 += __shfl_xor_sync(0xffffffffu, rs1, 2);
    if (tig == 0) { Rs[r0] = rs0; Rs[r1] = rs1; }
    __syncthreads();

    float inv0 = 1.0f / Rs[r0];
    float inv1 = 1.0f / Rs[r1];
    const float* bh = b1 + h * NH;
    float* d0 = g_h + (size_t)(i0 + r0) * (H1 * NH) + h * NH;
    float* d1 = g_h + (size_t)(i0 + r1) * (H1 * NH) + h * NH;
#pragma unroll
    for (int nt = 0; nt < 8; ++nt) {
        int cc = nt * 8 + 2 * tig;
        float2 bb = *(const float2*)(bh + cc);
        *(float2*)(d0 + cc) = make_float2(fmaxf(c[nt][0] * inv0 + bb.x, 0.f),
                                          fmaxf(c[nt][1] * inv0 + bb.y, 0.f));
        *(float2*)(d1 + cc) = make_float2(fmaxf(c[nt][2] * inv1 + bb.x, 0.f),
                                          fmaxf(c[nt][3] * inv1 + bb.y, 0.f));
    }
}

// ---------------- K3: feats2 = h @ W2 (K-split x8); factorized exps ------------
__global__ void k_gemm2(const float* __restrict__ W2, const float* __restrict__ as2,
                        const float* __restrict__ an2) {
    __shared__ float Ws[NF * NC];
    int tid = threadIdx.x;
    for (int u = tid; u < NF * NC; u += 256) Ws[u] = W2[u];
    __syncthreads();
    int row = blockIdx.x * 32 + (tid >> 3);
    int sl = tid & 7;                     // K slice: [sl*64, sl*64+64)
    const float* hr = g_h + (size_t)row * NF + sl * 64;
    float acc[NC] = {};
    for (int k = 0; k < 64; k += 4) {
        float4 xv = *(const float4*)&hr[k];
        const float* wp = &Ws[(sl * 64 + k) * NC];
#pragma unroll
        for (int f = 0; f < NC; ++f) {
            acc[f] = fmaf(xv.x, wp[f], acc[f]);
            acc[f] = fmaf(xv.y, wp[NC + f], acc[f]);
            acc[f] = fmaf(xv.z, wp[2 * NC + f], acc[f]);
            acc[f] = fmaf(xv.w, wp[3 * NC + f], acc[f]);
        }
    }
#pragma unroll
    for (int o = 4; o; o >>= 1)
#pragma unroll
        for (int f = 0; f < NC; ++f)
            acc[f] += __shfl_xor_sync(0xffffffffu, acc[f], o);
    if (sl == 0) {
        float sv = 0.f, nv = 0.f;
#pragma unroll
        for (int f = 0; f < NC; ++f) { sv = fmaf(acc[f], as2[f], sv); nv = fmaf(acc[f], an2[f], nv); }
        float4* fo = (float4*)&g_feats2[(size_t)row * NC];
        fo[0] = make_float4(acc[0], acc[1], acc[2], acc[3]);
        fo[1] = make_float4(acc[4], acc[5], acc[6], acc[7]);
        fo[2] = make_float4(acc[8], acc[9], acc[10], acc[11]);
        fo[3] = make_float4(acc[12], acc[13], acc[14], acc[15]);
        g_EG2[row] = make_float2(__expf(sv), __expf(0.2f * sv));
        g_FH2[row] = make_float2(__expf(nv), __expf(0.2f * nv));
    }
}

// ---------------- K4: layer-2 attention + relu + log_softmax -------------------
__global__ void k_attn2(const float* __restrict__ b2, float* __restrict__ out) {
    int i0 = blockIdx.x * 32;
    int tid = threadIdx.x;
    __shared__ float Ps[64][36];
    __shared__ float Fs[64][16];
    __shared__ float2 fhs[64];
    __shared__ float RsP[32][8];
    int pr = tid >> 3, pj = tid & 7;
    int irow = i0 + pr;
    float2 eg = g_EG2[irow];
    const unsigned* bi = g_adj + (size_t)irow * WPR;
    int tx = tid & 15, tq = tid >> 4;
    float acc0 = 0.f, acc1 = 0.f, rs = 0.f;

    for (int jt = 0; jt < Nn / 64; ++jt) {
        __syncthreads();
        ((float4*)&Fs[0][0])[tid] = ((const float4*)(g_feats2 + (size_t)jt * 64 * NC))[tid];
        if (tid < 64) fhs[tid] = g_FH2[jt * 64 + tid];
        __syncthreads();
        unsigned w0 = bi[jt * 2], w1 = bi[jt * 2 + 1];
#pragma unroll
        for (int k = 0; k < 8; ++k) {
            int j = pj + k * 8;
            unsigned bit = (j < 32) ? ((w0 >> j) & 1u) : ((w1 >> (j - 32)) & 1u);
            float2 fh = fhs[j];
            float p = bit ? fmaxf(eg.x * fh.x, eg.y * fh.y) : 0.f;
            rs += p;
            Ps[j][pr] = p;
        }
        __syncthreads();
#pragma unroll 8
        for (int j = 0; j < 64; ++j) {
            float b = Fs[j][tx];
            acc0 = fmaf(Ps[j][tq * 2], b, acc0);
            acc1 = fmaf(Ps[j][tq * 2 + 1], b, acc1);
        }
    }
    __syncthreads();
    RsP[pr][pj] = rs;
    __syncthreads();
    float s0 = 0.f, s1 = 0.f;
#pragma unroll
    for (int k = 0; k < 8; ++k) { s0 += RsP[tq * 2][k]; s1 += RsP[tq * 2 + 1][k]; }
    float bb = b2[tx];
    float v0 = fmaxf(acc0 / s0 + bb, 0.f);
    float v1 = fmaxf(acc1 / s1 + bb, 0.f);
    float m0 = v0, m1 = v1;
#pragma unroll
    for (int o = 8; o; o >>= 1) {
        m0 = fmaxf(m0, __shfl_xor_sync(0xffffffffu, m0, o));
        m1 = fmaxf(m1, __shfl_xor_sync(0xffffffffu, m1, o));
    }
    float e0 = __expf(v0 - m0), e1 = __expf(v1 - m1);
#pragma unroll
    for (int o = 8; o; o >>= 1) {
        e0 += __shfl_xor_sync(0xffffffffu, e0, o);
        e1 += __shfl_xor_sync(0xffffffffu, e1, o);
    }
    out[(size_t)(i0 + tq * 2 + 0) * NC + tx] = v0 - (logf(e0) + m0);
    out[(size_t)(i0 + tq * 2 + 1) * NC + tx] = v1 - (logf(e1) + m1);
}

// ---------------- launcher ----------------
extern "C" void kernel_launch(void* const* d_in, const int* in_sizes, int n_in,
                              void* d_out, int out_size) {
    (void)in_sizes; (void)n_in; (void)out_size;
    const float* x   = (const float*)d_in[0];
    const int*   adj = (const int*)d_in[1];
    const float* W1  = (const float*)d_in[2];
    const float* b1  = (const float*)d_in[3];
    const float* as1 = (const float*)d_in[4];
    const float* an1 = (const float*)d_in[5];
    const float* W2  = (const float*)d_in[6];
    const float* b2  = (const float*)d_in[7];
    const float* as2 = (const float*)d_in[8];
    const float* an2 = (const float*)d_in[9];
    float* out = (float*)d_out;

    k_adjbits<<<2048, 256>>>(adj);
    k_wt<<<dim3(NF / 32, NH / 32, H1), dim3(32, 8)>>>(W1);
    k_gemm1_mma<<<dim3(Nn / 128, H1), 256>>>(x);
    k_transp<<<dim3(Nn / 32, NH / 32, H1), dim3(32, 8)>>>();
    k_attnvec1<<<(H1 * Nn) / 8, 256>>>(as1, an1);
    k_attn1_mma<<<dim3(Nn / 128, H1), 256>>>(b1);
    k_gemm2<<<Nn / 32, 256>>>(W2, as2, an2);
    k_attn2<<<Nn / 32, 256>>>(b2, out);
}

// round 9
// speedup vs baseline: 5.4611x; 1.0805x over previous
#include <cuda_runtime.h>
#include <cuda_bf16.h>
#include <cstdint>

#define Nn 4096
#define NF 512
#define NH 64
#define H1 8
#define NC 16
#define WPR 128   // words per adjacency row (4096/32)

// ---------------- scratch (static device globals; no allocation) ----------------
// All 16B-aligned: vector (float4/uint4) and cp.async.16 accesses require it.
__device__ __align__(16) unsigned g_adj[Nn * WPR];            // 2 MB bitmask
__device__ __align__(16) float g_feats1[H1 * Nn * NH];        // 8 MB  [h][i][f]
// g_ftb: MMA-staged layout: [h][jt(64)][f(64)][64 j, pair-permuted] bf16
__device__ __align__(16) __nv_bfloat16 g_ftb[H1 * NH * Nn];   // 4 MB
__device__ __align__(16) float g_wt[H1 * NH * NF];            // 1 MB  [h][f][k]
__device__ __align__(16) float2 g_EG1[H1 * Nn];               // (exp(s), exp(.2 s))
__device__ __align__(16) float2 g_FH1[H1 * Nn];               // (exp(nb), exp(.2 nb))
__device__ __align__(16) float g_h[Nn * (H1 * NH)];           // 8 MB
__device__ __align__(16) float g_feats2[Nn * NC];
__device__ __align__(16) float2 g_EG2[Nn];
__device__ __align__(16) float2 g_FH2[Nn];

// ---------------- helpers ----------------
__device__ __forceinline__ uint32_t tf32r(float f) {
    uint32_t r; asm("cvt.rna.tf32.f32 %0, %1;" : "=r"(r) : "f"(f)); return r;
}
__device__ __forceinline__ float tf32f(float f) {
    uint32_t r = tf32r(f); return __uint_as_float(r);
}
__device__ __forceinline__ void mma_tf32(float* c,
                                         uint32_t a0, uint32_t a1, uint32_t a2, uint32_t a3,
                                         uint32_t b0, uint32_t b1) {
    asm volatile(
        "mma.sync.aligned.m16n8k8.row.col.f32.tf32.tf32.f32 "
        "{%0,%1,%2,%3}, {%4,%5,%6,%7}, {%8,%9}, {%0,%1,%2,%3};"
        : "+f"(c[0]), "+f"(c[1]), "+f"(c[2]), "+f"(c[3])
        : "r"(a0), "r"(a1), "r"(a2), "r"(a3), "r"(b0), "r"(b1));
}
__device__ __forceinline__ void mma_bf16(float* c,
                                         uint32_t a0, uint32_t a1, uint32_t a2, uint32_t a3,
                                         uint32_t b0, uint32_t b1) {
    asm volatile(
        "mma.sync.aligned.m16n8k16.row.col.f32.bf16.bf16.f32 "
        "{%0,%1,%2,%3}, {%4,%5,%6,%7}, {%8,%9}, {%0,%1,%2,%3};"
        : "+f"(c[0]), "+f"(c[1]), "+f"(c[2]), "+f"(c[3])
        : "r"(a0), "r"(a1), "r"(a2), "r"(a3), "r"(b0), "r"(b1));
}
__device__ __forceinline__ uint32_t pack_bf16x2(float lo, float hi) {
    uint32_t d;
    asm("cvt.rn.bf16x2.f32 %0, %1, %2;" : "=r"(d) : "f"(hi), "f"(lo));
    return d;
}
__device__ __forceinline__ void cp16(void* dst, const void* src) {
    uint32_t d = (uint32_t)__cvta_generic_to_shared(dst);
    asm volatile("cp.async.cg.shared.global [%0], [%1], 16;" :: "r"(d), "l"(src) : "memory");
}
__device__ __forceinline__ void cp4(void* dst, const void* src) {
    uint32_t d = (uint32_t)__cvta_generic_to_shared(dst);
    asm volatile("cp.async.ca.shared.global [%0], [%1], 4;" :: "r"(d), "l"(src) : "memory");
}
__device__ __forceinline__ void cp_commit() {
    asm volatile("cp.async.commit_group;" ::: "memory");
}
__device__ __forceinline__ void cp_wait_all() {
    asm volatile("cp.async.wait_group 0;" ::: "memory");
}

// ---------------- K1: prep = adjacency bitmask + W1 transpose/round ------------
__global__ void k_prep(const int* __restrict__ adj, const float* __restrict__ W1) {
    __shared__ float t[32][33];
    if (blockIdx.x < 2048) {
        int gw = blockIdx.x * 8 + (threadIdx.x >> 5);
        int lane = threadIdx.x & 31;
        int row = gw >> 2, q = gw & 3;
        const int* base = adj + (size_t)row * Nn + q * 1024;
        unsigned* wbase = g_adj + row * WPR + q * 32;
#pragma unroll 4
        for (int w = 0; w < 32; ++w) {
            unsigned m = __ballot_sync(0xffffffffu, base[w * 32 + lane] > 0);
            if (lane == 0) wbase[w] = m;
        }
    } else {
        int idx = blockIdx.x - 2048;           // 0..255
        int h = idx >> 5;
        int r = idx & 31;
        int kt = (r >> 1) * 32, ft = (r & 1) * 32;
        int x = threadIdx.x & 31, y = threadIdx.x >> 5;
        const float* src = W1 + (size_t)h * NF * NH;
#pragma unroll
        for (int rr = y; rr < 32; rr += 8)
            t[rr][x] = src[(size_t)(kt + rr) * NH + ft + x];
        __syncthreads();
        float* dst = g_wt + (size_t)h * NH * NF;
#pragma unroll
        for (int rr = y; rr < 32; rr += 8)
            dst[(size_t)(ft + rr) * NF + kt + x] = tf32f(t[x][rr]);
    }
}

// ---------------- K2: feats1[h] = x @ W1[h]  via mma.sync tf32 -----------------
__global__ void __launch_bounds__(256, 2) k_gemm1_mma(const float* __restrict__ x) {
    int h = blockIdx.y;
    int i0 = blockIdx.x * 128;
    int tid = threadIdx.x, wid = tid >> 5, lane = tid & 31;
    int gid = lane >> 2, tig = lane & 3;
    __shared__ float Xs[128][40];    // 160B rows: float4-safe
    __shared__ float Wt_s[64][40];

    int r0 = wid * 16 + gid, r1 = r0 + 8;
    float c[8][4] = {};

    int srow = tid >> 1, shalf = tid & 1;
    int sf = tid >> 2, sq = tid & 3;
    const float* xsrc = x + (size_t)(i0 + srow) * NF + shalf * 16;
    const float* wsrc = g_wt + ((size_t)h * NH + sf) * NF + sq * 8;

    for (int kc = 0; kc < NF / 32; ++kc) {
        __syncthreads();
#pragma unroll
        for (int v = 0; v < 4; ++v) {
            float4 t = *(const float4*)(xsrc + kc * 32 + v * 4);
            t.x = tf32f(t.x); t.y = tf32f(t.y); t.z = tf32f(t.z); t.w = tf32f(t.w);
            *(float4*)&Xs[srow][shalf * 16 + v * 4] = t;
        }
        {
            float4 v0 = *(const float4*)(wsrc + kc * 32);
            float4 v1 = *(const float4*)(wsrc + kc * 32 + 4);
            *(float4*)&Wt_s[sf][sq * 8] = v0;
            *(float4*)&Wt_s[sf][sq * 8 + 4] = v1;
        }
        __syncthreads();
#pragma unroll
        for (int ks = 0; ks < 4; ++ks) {
            int k0 = ks * 8 + 2 * tig;
            float2 a02 = *(const float2*)&Xs[r0][k0];
            float2 a13 = *(const float2*)&Xs[r1][k0];
            uint32_t a0 = __float_as_uint(a02.x), a2 = __float_as_uint(a02.y);
            uint32_t a1 = __float_as_uint(a13.x), a3 = __float_as_uint(a13.y);
#pragma unroll
            for (int nt = 0; nt < 8; ++nt) {
                float2 b = *(const float2*)&Wt_s[nt * 8 + gid][k0];
                mma_tf32(c[nt], a0, a1, a2, a3, __float_as_uint(b.x), __float_as_uint(b.y));
            }
        }
    }
    float* o0 = g_feats1 + ((size_t)h * Nn + i0 + r0) * NH;
    float* o1 = g_feats1 + ((size_t)h * Nn + i0 + r1) * NH;
#pragma unroll
    for (int nt = 0; nt < 8; ++nt) {
        int cc = nt * 8 + 2 * tig;
        *(float2*)(o0 + cc) = make_float2(c[nt][0], c[nt][1]);
        *(float2*)(o1 + cc) = make_float2(c[nt][2], c[nt][3]);
    }
}

// ---------------- K3: ftprep = transpose+permute feats1 -> g_ftb, + EG/FH ------
// NOTE: tile rows are 65 floats (260B, NOT 16B-aligned) -> smem stores must be
// scalar; global loads stay vectorized (float4 into registers).
__global__ void __launch_bounds__(256) k_ftprep(const float* __restrict__ as1,
                                                const float* __restrict__ an1) {
    int jt = blockIdx.x, h = blockIdx.y;
    __shared__ float tile[64][65];
    __shared__ float av[64], nv[64];
    int tid = threadIdx.x;
    {
        int r = tid >> 2, fq = (tid & 3) * 16;
        const float* src = g_feats1 + ((size_t)h * Nn + jt * 64 + r) * NH + fq;
#pragma unroll
        for (int v = 0; v < 4; ++v) {
            float4 t = *(const float4*)(src + v * 4);   // aligned global load
            tile[r][fq + v * 4 + 0] = t.x;              // scalar smem stores
            tile[r][fq + v * 4 + 1] = t.y;
            tile[r][fq + v * 4 + 2] = t.z;
            tile[r][fq + v * 4 + 3] = t.w;
        }
    }
    if (tid < 64) { av[tid] = as1[h * NH + tid]; nv[tid] = an1[h * NH + tid]; }
    __syncthreads();

    // A: write permuted bf16 tile
    {
        int f = tid >> 2, g = tid & 3;
        uint32_t w[8];
#pragma unroll
        for (int s = 0; s < 8; ++s) {
            int q = (s & 1) ? (s >> 1) + 4 : (s >> 1);
            int j = g * 16 + 2 * q;
            w[s] = pack_bf16x2(tile[j][f], tile[j + 1][f]);
        }
        uint32_t* dst = (uint32_t*)g_ftb + (((size_t)h * 64 + jt) * NH + f) * 32 + g * 8;
        *(uint4*)dst = make_uint4(w[0], w[1], w[2], w[3]);
        *(uint4*)(dst + 4) = make_uint4(w[4], w[5], w[6], w[7]);
    }
    // B: s/nb dot products -> EG/FH
    {
        int j = tid >> 2, q4 = (tid & 3) * 16;
        float vs = 0.f, vn = 0.f;
#pragma unroll
        for (int u = 0; u < 16; ++u) {
            float xv = tile[j][q4 + u];
            vs = fmaf(xv, av[q4 + u], vs);
            vn = fmaf(xv, nv[q4 + u], vn);
        }
        vs += __shfl_xor_sync(0xffffffffu, vs, 1);
        vs += __shfl_xor_sync(0xffffffffu, vs, 2);
        vn += __shfl_xor_sync(0xffffffffu, vn, 1);
        vn += __shfl_xor_sync(0xffffffffu, vn, 2);
        if ((tid & 3) == 0) {
            int gi = h * Nn + jt * 64 + j;
            g_EG1[gi] = make_float2(__expf(vs), __expf(0.2f * vs));
            g_FH1[gi] = make_float2(__expf(vn), __expf(0.2f * vn));
        }
    }
}

// ---------------- K4: layer-1 attention, bf16 mma + cp.async pipeline ----------
__global__ void __launch_bounds__(256, 2) k_attn1_mma(const float* __restrict__ b1) {
    int h = blockIdx.y;
    int i0 = blockIdx.x * 128;
    int tid = threadIdx.x, wid = tid >> 5, lane = tid & 31;
    int gid = lane >> 2, tig = lane & 3;

    __shared__ __align__(16) __nv_bfloat16 Ft_s[2][64][80];  // 160B rows
    __shared__ __align__(16) float2 FHs[2][64];
    __shared__ __align__(16) unsigned adjs[2][256];
    __shared__ float Rs[128];

    int r0 = wid * 16 + gid, r1 = r0 + 8;
    float2 eg0 = g_EG1[h * Nn + i0 + r0];
    float2 eg1 = g_EG1[h * Nn + i0 + r1];
    float c[8][4] = {};
    float rs0 = 0.f, rs1 = 0.f;

    const float2* fhsrc = g_FH1 + h * Nn;
    int arow = tid >> 1, ahalf = tid & 1;
    const unsigned* adjsrc = g_adj + (size_t)(i0 + arow) * WPR + ahalf;

    auto stage = [&](int jt, int buf) {
        const char* fbase = (const char*)(g_ftb + ((size_t)(h * 64 + jt) * NH) * 64);
        int c0 = tid, c1 = tid + 256;
        cp16(&Ft_s[buf][c0 >> 3][(c0 & 7) * 8], fbase + c0 * 16);
        cp16(&Ft_s[buf][c1 >> 3][(c1 & 7) * 8], fbase + c1 * 16);
        cp4(&adjs[buf][tid], adjsrc + jt * 2);
        if (tid < 32) cp16(&FHs[buf][tid * 2], fhsrc + jt * 64 + tid * 2);
        cp_commit();
    };

    stage(0, 0);
    for (int jt = 0; jt < Nn / 64; ++jt) {
        int buf = jt & 1;
        cp_wait_all();
        __syncthreads();
        if (jt + 1 < Nn / 64) stage(jt + 1, buf ^ 1);

        unsigned wa0 = adjs[buf][r0 * 2], wb0 = adjs[buf][r0 * 2 + 1];
        unsigned wa1 = adjs[buf][r1 * 2], wb1 = adjs[buf][r1 * 2 + 1];
#pragma unroll
        for (int ks = 0; ks < 4; ++ks) {
            int jb2 = ks * 16;
            unsigned sw0 = ((ks & 2) ? wb0 : wa0) >> ((ks & 1) * 16);
            unsigned sw1 = ((ks & 2) ? wb1 : wa1) >> ((ks & 1) * 16);
            int j0 = 2 * tig, j2 = j0 + 8;
            float2 fh0 = FHs[buf][jb2 + j0];
            float2 fh1 = FHs[buf][jb2 + j0 + 1];
            float2 fh2 = FHs[buf][jb2 + j2];
            float2 fh3 = FHs[buf][jb2 + j2 + 1];
            float p00 = ((sw0 >> j0) & 1u)       ? fmaxf(eg0.x * fh0.x, eg0.y * fh0.y) : 0.f;
            float p01 = ((sw0 >> (j0 + 1)) & 1u) ? fmaxf(eg0.x * fh1.x, eg0.y * fh1.y) : 0.f;
            float p02 = ((sw0 >> j2) & 1u)       ? fmaxf(eg0.x * fh2.x, eg0.y * fh2.y) : 0.f;
            float p03 = ((sw0 >> (j2 + 1)) & 1u) ? fmaxf(eg0.x * fh3.x, eg0.y * fh3.y) : 0.f;
            float p10 = ((sw1 >> j0) & 1u)       ? fmaxf(eg1.x * fh0.x, eg1.y * fh0.y) : 0.f;
            float p11 = ((sw1 >> (j0 + 1)) & 1u) ? fmaxf(eg1.x * fh1.x, eg1.y * fh1.y) : 0.f;
            float p12 = ((sw1 >> j2) & 1u)       ? fmaxf(eg1.x * fh2.x, eg1.y * fh2.y) : 0.f;
            float p13 = ((sw1 >> (j2 + 1)) & 1u) ? fmaxf(eg1.x * fh3.x, eg1.y * fh3.y) : 0.f;
            rs0 += (p00 + p01) + (p02 + p03);
            rs1 += (p10 + p11) + (p12 + p13);
            uint32_t a0 = pack_bf16x2(p00, p01);
            uint32_t a1 = pack_bf16x2(p10, p11);
            uint32_t a2 = pack_bf16x2(p02, p03);
            uint32_t a3 = pack_bf16x2(p12, p13);
#pragma unroll
            for (int nt = 0; nt < 8; ++nt) {
                uint2 bb = *(const uint2*)((const char*)&Ft_s[buf][0][0] +
                                           (nt * 8 + gid) * 160 + ks * 32 + tig * 8);
                mma_bf16(c[nt], a0, a1, a2, a3, bb.x, bb.y);
            }
        }
    }
    rs0 += __shfl_xor_sync(0xffffffffu, rs0, 1);
    rs0 += __shfl_xor_sync(0xffffffffu, rs0, 2);
    rs1 += __shfl_xor_sync(0xffffffffu, rs1, 1);
    rs1 += __shfl_xor_sync(0xffffffffu, rs1, 2);
    if (tig == 0) { Rs[r0] = rs0; Rs[r1] = rs1; }
    __syncthreads();

    float inv0 = 1.0f / Rs[r0];
    float inv1 = 1.0f / Rs[r1];
    const float* bh = b1 + h * NH;
    float* d0 = g_h + (size_t)(i0 + r0) * (H1 * NH) + h * NH;
    float* d1 = g_h + (size_t)(i0 + r1) * (H1 * NH) + h * NH;
#pragma unroll
    for (int nt = 0; nt < 8; ++nt) {
        int cc = nt * 8 + 2 * tig;
        float2 bb = *(const float2*)(bh + cc);
        *(float2*)(d0 + cc) = make_float2(fmaxf(c[nt][0] * inv0 + bb.x, 0.f),
                                          fmaxf(c[nt][1] * inv0 + bb.y, 0.f));
        *(float2*)(d1 + cc) = make_float2(fmaxf(c[nt][2] * inv1 + bb.x, 0.f),
                                          fmaxf(c[nt][3] * inv1 + bb.y, 0.f));
    }
}

// ---------------- K5: feats2 = h @ W2 (K-split x8); factorized exps ------------
__global__ void k_gemm2(const float* __restrict__ W2, const float* __restrict__ as2,
                        const float* __restrict__ an2) {
    __shared__ float Ws[NF * NC];
    int tid = threadIdx.x;
    for (int u = tid; u < NF * NC; u += 256) Ws[u] = W2[u];
    __syncthreads();
    int row = blockIdx.x * 32 + (tid >> 3);
    int sl = tid & 7;
    const float* hr = g_h + (size_t)row * NF + sl * 64;
    float acc[NC] = {};
    for (int k = 0; k < 64; k += 4) {
        float4 xv = *(const float4*)&hr[k];
        const float* wp = &Ws[(sl * 64 + k) * NC];
#pragma unroll
        for (int f = 0; f < NC; ++f) {
            acc[f] = fmaf(xv.x, wp[f], acc[f]);
            acc[f] = fmaf(xv.y, wp[NC + f], acc[f]);
            acc[f] = fmaf(xv.z, wp[2 * NC + f], acc[f]);
            acc[f] = fmaf(xv.w, wp[3 * NC + f], acc[f]);
        }
    }
#pragma unroll
    for (int o = 4; o; o >>= 1)
#pragma unroll
        for (int f = 0; f < NC; ++f)
            acc[f] += __shfl_xor_sync(0xffffffffu, acc[f], o);
    if (sl == 0) {
        float sv = 0.f, nv = 0.f;
#pragma unroll
        for (int f = 0; f < NC; ++f) { sv = fmaf(acc[f], as2[f], sv); nv = fmaf(acc[f], an2[f], nv); }
        float4* fo = (float4*)&g_feats2[(size_t)row * NC];
        fo[0] = make_float4(acc[0], acc[1], acc[2], acc[3]);
        fo[1] = make_float4(acc[4], acc[5], acc[6], acc[7]);
        fo[2] = make_float4(acc[8], acc[9], acc[10], acc[11]);
        fo[3] = make_float4(acc[12], acc[13], acc[14], acc[15]);
        g_EG2[row] = make_float2(__expf(sv), __expf(0.2f * sv));
        g_FH2[row] = make_float2(__expf(nv), __expf(0.2f * nv));
    }
}

// ---------------- K6: layer-2 attention + relu + log_softmax -------------------
__global__ void k_attn2(const float* __restrict__ b2, float* __restrict__ out) {
    int i0 = blockIdx.x * 32;
    int tid = threadIdx.x;
    __shared__ float Ps[64][36];
    __shared__ __align__(16) float Fs[64][16];
    __shared__ float2 fhs[64];
    __shared__ float RsP[32][8];
    int pr = tid >> 3, pj = tid & 7;
    int irow = i0 + pr;
    float2 eg = g_EG2[irow];
    const unsigned* bi = g_adj + (size_t)irow * WPR;
    int tx = tid & 15, tq = tid >> 4;
    float acc0 = 0.f, acc1 = 0.f, rs = 0.f;

    for (int jt = 0; jt < Nn / 64; ++jt) {
        __syncthreads();
        ((float4*)&Fs[0][0])[tid] = ((const float4*)(g_feats2 + (size_t)jt * 64 * NC))[tid];
        if (tid < 64) fhs[tid] = g_FH2[jt * 64 + tid];
        __syncthreads();
        unsigned w0 = bi[jt * 2], w1 = bi[jt * 2 + 1];
#pragma unroll
        for (int k = 0; k < 8; ++k) {
            int j = pj + k * 8;
            unsigned bit = (j < 32) ? ((w0 >> j) & 1u) : ((w1 >> (j - 32)) & 1u);
            float2 fh = fhs[j];
            float p = bit ? fmaxf(eg.x * fh.x, eg.y * fh.y) : 0.f;
            rs += p;
            Ps[j][pr] = p;
        }
        __syncthreads();
#pragma unroll 8
        for (int j = 0; j < 64; ++j) {
            float b = Fs[j][tx];
            acc0 = fmaf(Ps[j][tq * 2], b, acc0);
            acc1 = fmaf(Ps[j][tq * 2 + 1], b, acc1);
        }
    }
    __syncthreads();
    RsP[pr][pj] = rs;
    __syncthreads();
    float s0 = 0.f, s1 = 0.f;
#pragma unroll
    for (int k = 0; k < 8; ++k) { s0 += RsP[tq * 2][k]; s1 += RsP[tq * 2 + 1][k]; }
    float bb = b2[tx];
    float v0 = fmaxf(acc0 / s0 + bb, 0.f);
    float v1 = fmaxf(acc1 / s1 + bb, 0.f);
    float m0 = v0, m1 = v1;
#pragma unroll
    for (int o = 8; o; o >>= 1) {
        m0 = fmaxf(m0, __shfl_xor_sync(0xffffffffu, m0, o));
        m1 = fmaxf(m1, __shfl_xor_sync(0xffffffffu, m1, o));
    }
    float e0 = __expf(v0 - m0), e1 = __expf(v1 - m1);
#pragma unroll
    for (int o = 8; o; o >>= 1) {
        e0 += __shfl_xor_sync(0xffffffffu, e0, o);
        e1 += __shfl_xor_sync(0xffffffffu, e1, o);
    }
    out[(size_t)(i0 + tq * 2 + 0) * NC + tx] = v0 - (logf(e0) + m0);
    out[(size_t)(i0 + tq * 2 + 1) * NC + tx] = v1 - (logf(e1) + m1);
}

// ---------------- launcher ----------------
extern "C" void kernel_launch(void* const* d_in, const int* in_sizes, int n_in,
                              void* d_out, int out_size) {
    (void)in_sizes; (void)n_in; (void)out_size;
    const float* x   = (const float*)d_in[0];
    const int*   adj = (const int*)d_in[1];
    const float* W1  = (const float*)d_in[2];
    const float* b1  = (const float*)d_in[3];
    const float* as1 = (const float*)d_in[4];
    const float* an1 = (const float*)d_in[5];
    const float* W2  = (const float*)d_in[6];
    const float* b2  = (const float*)d_in[7];
    const float* as2 = (const float*)d_in[8];
    const float* an2 = (const float*)d_in[9];
    float* out = (float*)d_out;

    k_prep<<<2048 + 256, 256>>>(adj, W1);                    // 1
    k_gemm1_mma<<<dim3(Nn / 128, H1), 256>>>(x);             // 2
    k_ftprep<<<dim3(Nn / 64, H1), 256>>>(as1, an1);          // 3
    k_attn1_mma<<<dim3(Nn / 128, H1), 256>>>(b1);            // 4  <- profiled launch
    k_gemm2<<<Nn / 32, 256>>>(W2, as2, an2);                 // 5
    k_attn2<<<Nn / 32, 256>>>(b2, out);                      // 6
}